// round 4
// baseline (speedup 1.0000x reference)
#include <cuda_runtime.h>
#include <cuda_bf16.h>
#include <cstdint>

#define N_USER 100000
#define N_ITEM 50000
#define N_TOTAL (N_USER + N_ITEM)   // 150000
#define D 64
#define NNZ 4000000
#define B 2048
#define NEG (4 * B)                  // 8192
#define NSLOTS (B + B + NEG)         // 12288
#define NWORDS ((N_TOTAL + 31) / 32) // 4688 words = 18.75 KB bitset
#define MAXDEG 128                   // mean deg ~27; P(>127) ~ 1e-42

// Device scratch (zero-initialized at load; K5 restores all-zero every call).
__device__ int      g_rowmap[N_TOTAL];                 // 0 = unclaimed, else owner_slot+1
__device__ int      g_rowof[NSLOTS];                   // 0 = not owner, else row+1
__device__ int      g_cnt[NSLOTS];                     // edges appended per owner slot
__device__ int2     g_edges[(size_t)NSLOTS * MAXDEG];  // (col, val-bits), 12.6 MB
__device__ unsigned g_flags[NWORDS];                   // needed-row bitset (L1-hot)

// slot -> global row id in [0, N_TOTAL)
__device__ __forceinline__ int slot_row(int s, const int* __restrict__ users,
                                        const int* __restrict__ pos,
                                        const int* __restrict__ neg) {
    if (s < B) return users[s];
    if (s < 2 * B) return N_USER + pos[s - B];
    return N_USER + neg[s - 2 * B];
}

// ---------------------------------------------------------------------------
// K2: claim rows. One thread per slot. Winner of the CAS owns the row's
// edge bucket; it also sets the bitset bit for the cheap K3a probe.
// ---------------------------------------------------------------------------
__global__ void k_claim(const int* __restrict__ users,
                        const int* __restrict__ pos,
                        const int* __restrict__ neg) {
    int s = blockIdx.x * blockDim.x + threadIdx.x;
    if (s >= NSLOTS) return;
    int r = slot_row(s, users, pos, neg);
    if (atomicCAS(&g_rowmap[r], 0, s + 1) == 0) {
        g_rowof[s] = r + 1;
        atomicOr(&g_flags[r >> 5], 1u << (r & 31));
    }
}

// ---------------------------------------------------------------------------
// K3a: scan all edges; active ones append (col, val) to the owner's bucket.
// ---------------------------------------------------------------------------
__global__ void k_build(const int* __restrict__ adj_row,
                        const int* __restrict__ adj_col,
                        const float* __restrict__ adj_val) {
    int i = blockIdx.x * blockDim.x + threadIdx.x;
    if (i >= NNZ) return;
    int r = __ldg(adj_row + i);
    if ((g_flags[r >> 5] >> (r & 31)) & 1u) {
        int   c = __ldg(adj_col + i);
        float v = __ldg(adj_val + i);
        int sid = g_rowmap[r] - 1;                 // valid: K2 completed
        int idx = atomicAdd(&g_cnt[sid], 1);
        if (idx < MAXDEG)
            g_edges[(size_t)sid * MAXDEG + idx] = make_int2(c, __float_as_int(v));
    }
}

// ---------------------------------------------------------------------------
// K3b: one warp per OWNER slot. Register-accumulate the row's edges
// (coalesced float2 gathers, no atomics) and write the blended result
// directly to the output row of the owner slot.
// ---------------------------------------------------------------------------
__global__ void k_accum(const float* __restrict__ user_emb,
                        const float* __restrict__ item_emb,
                        float* __restrict__ out) {
    int gtid = blockIdx.x * blockDim.x + threadIdx.x;
    int warp = gtid >> 5;
    int lane = gtid & 31;
    if (warp >= NSLOTS) return;
    int ro = g_rowof[warp];
    if (ro == 0) return;                            // not an owner
    int r = ro - 1;
    int cnt = g_cnt[warp];
    cnt = cnt < MAXDEG ? cnt : MAXDEG;
    const int2* el = g_edges + (size_t)warp * MAXDEG;

    float ax = 0.0f, ay = 0.0f;
#pragma unroll 4
    for (int e = 0; e < cnt; e++) {
        int2 p = __ldg(el + e);                     // warp-broadcast load
        const float* src = (p.x < N_USER)
                               ? (user_emb + (size_t)p.x * D)
                               : (item_emb + (size_t)(p.x - N_USER) * D);
        float  v  = __int_as_float(p.y);
        float2 ev = __ldg(reinterpret_cast<const float2*>(src) + lane);
        ax = fmaf(v, ev.x, ax);
        ay = fmaf(v, ev.y, ay);
    }

    const float* e0 = (r < N_USER) ? (user_emb + (size_t)r * D)
                                   : (item_emb + (size_t)(r - N_USER) * D);
    float2 e = __ldg(reinterpret_cast<const float2*>(e0) + lane);
    float2 o;
    o.x = (e.x + 3.0f * ax) * 0.25f;
    o.y = (e.y + 3.0f * ay) * 0.25f;
    reinterpret_cast<float2*>(out)[(size_t)warp * (D / 2) + lane] = o;
}

// ---------------------------------------------------------------------------
// K4: duplicate slots copy the owner's already-written output row.
// ---------------------------------------------------------------------------
__global__ void k_fill_dups(const int* __restrict__ users,
                            const int* __restrict__ pos,
                            const int* __restrict__ neg,
                            float* __restrict__ out) {
    int gtid = blockIdx.x * blockDim.x + threadIdx.x;
    int warp = gtid >> 5;
    int lane = gtid & 31;
    if (warp >= NSLOTS) return;
    int r = slot_row(warp, users, pos, neg);
    int owner = g_rowmap[r] - 1;
    if (owner == warp) return;                      // owner already wrote
    float2 v = reinterpret_cast<const float2*>(out)[(size_t)owner * (D / 2) + lane];
    reinterpret_cast<float2*>(out)[(size_t)warp * (D / 2) + lane] = v;
}

// ---------------------------------------------------------------------------
// K5: restore all device state to zero for the next graph replay.
// ---------------------------------------------------------------------------
__global__ void k_reset(const int* __restrict__ users,
                        const int* __restrict__ pos,
                        const int* __restrict__ neg) {
    int s = blockIdx.x * blockDim.x + threadIdx.x;
    if (s >= NSLOTS) return;
    int r = slot_row(s, users, pos, neg);
    g_rowmap[r] = 0;          // racing identical zeros — benign
    g_flags[r >> 5] = 0u;     // racing identical zeros — benign
    g_rowof[s] = 0;
    g_cnt[s] = 0;
}

// ---------------------------------------------------------------------------
// launch
// ---------------------------------------------------------------------------
extern "C" void kernel_launch(void* const* d_in, const int* in_sizes, int n_in,
                              void* d_out, int out_size) {
    const int*   users    = (const int*)d_in[0];
    const int*   pos      = (const int*)d_in[1];
    const int*   neg      = (const int*)d_in[2];
    // d_in[3] mask, d_in[4] norm_adj: unused placeholders
    const float* user_emb = (const float*)d_in[5];
    const float* item_emb = (const float*)d_in[6];
    const int*   adj_row  = (const int*)d_in[7];
    const int*   adj_col  = (const int*)d_in[8];
    const float* adj_val  = (const float*)d_in[9];
    float* out = (float*)d_out;

    (void)in_sizes; (void)n_in; (void)out_size;

    {   // K2: claim (1 thread per slot)
        int threads = 256, blocks = (NSLOTS + threads - 1) / threads;
        k_claim<<<blocks, threads>>>(users, pos, neg);
    }
    {   // K3a: build edge buckets (1 thread per edge)
        int threads = 256, blocks = (NNZ + threads - 1) / threads;
        k_build<<<blocks, threads>>>(adj_row, adj_col, adj_val);
    }
    {   // K3b: accumulate + blend + write owner rows (1 warp per slot)
        int threads = 256, blocks = (NSLOTS * 32 + threads - 1) / threads;
        k_accum<<<blocks, threads>>>(user_emb, item_emb, out);
    }
    {   // K4: copy owner rows into duplicate slots
        int threads = 256, blocks = (NSLOTS * 32 + threads - 1) / threads;
        k_fill_dups<<<blocks, threads>>>(users, pos, neg, out);
    }
    {   // K5: reset device state for next replay
        int threads = 256, blocks = (NSLOTS + threads - 1) / threads;
        k_reset<<<blocks, threads>>>(users, pos, neg);
    }
}

// round 5
// speedup vs baseline: 1.5247x; 1.5247x over previous
#include <cuda_runtime.h>
#include <cuda_bf16.h>
#include <cstdint>

#define N_USER 100000
#define N_ITEM 50000
#define N_TOTAL (N_USER + N_ITEM)   // 150000
#define D 64
#define NNZ 4000000
#define B 2048
#define NEG (4 * B)                  // 8192
#define NSLOTS (B + B + NEG)         // 12288
#define NWORDS ((N_TOTAL + 31) / 32) // 4688 words = 18.75 KB bitset

#define EPT 4                        // edges per thread in scan (int4)
#define SCAN_THREADS 256
#define EDGES_PER_BLOCK (SCAN_THREADS * EPT)   // 1024
#define MAX_HITS 192                 // mean hits/block ~77, sigma ~8.5 -> huge margin

// Scratch (zero-initialized at module load; K4 restores flags to zero each call,
// K2 zeroes the acc rows it will use each call).
__device__ float    g_acc[(size_t)N_TOTAL * D];   // 38.4 MB
__device__ unsigned g_flags[NWORDS];              // 18.75 KB (L1-hot)

// slot -> global row id in [0, N_TOTAL)
__device__ __forceinline__ int slot_row(int s, const int* __restrict__ users,
                                        const int* __restrict__ pos,
                                        const int* __restrict__ neg) {
    if (s < B) return users[s];
    if (s < 2 * B) return N_USER + pos[s - B];
    return N_USER + neg[s - 2 * B];
}

// ---------------------------------------------------------------------------
// K2: mark needed rows + zero their acc rows. TWO slots per warp:
// lanes 0-15 handle slot 2w, lanes 16-31 handle slot 2w+1 (float4 zeroing).
// ---------------------------------------------------------------------------
__global__ void k_mark_and_zero(const int* __restrict__ users,
                                const int* __restrict__ pos,
                                const int* __restrict__ neg) {
    int gtid = blockIdx.x * blockDim.x + threadIdx.x;
    int warp = gtid >> 5;
    int lane = gtid & 31;
    int half = lane >> 4;
    int l    = lane & 15;
    int s = warp * 2 + half;
    if (s >= NSLOTS) return;
    int r = slot_row(s, users, pos, neg);           // broadcast load per half
    if (l == 0) atomicOr(&g_flags[r >> 5], 1u << (r & 31));
    float4 z = make_float4(0.f, 0.f, 0.f, 0.f);
    reinterpret_cast<float4*>(g_acc + (size_t)r * D)[l] = z;
}

// ---------------------------------------------------------------------------
// K3: filtered SpMM with block-shared hit staging.
// Scan: each thread probes 4 edges (one int4 row load), pushes hits to smem.
// Drain: half-warp per hit — LDS broadcast of (i,row), float4 gather of
// e0[col], red.global.add.v4.f32 into g_acc[row].
// ---------------------------------------------------------------------------
__global__ void k_spmm_filtered(const int* __restrict__ adj_row,
                                const int* __restrict__ adj_col,
                                const float* __restrict__ adj_val,
                                const float* __restrict__ user_emb,
                                const float* __restrict__ item_emb) {
    __shared__ int  s_cnt;
    __shared__ int2 s_hits[MAX_HITS];               // (edge index, row)

    int tid = threadIdx.x;
    if (tid == 0) s_cnt = 0;
    __syncthreads();

    // ---- scan phase: 4 edges per thread via one int4 load ----
    int base = (blockIdx.x * SCAN_THREADS + tid) * EPT;
    if (base < NNZ) {                                // NNZ % 4 == 0 -> full int4 safe
        int4 r4 = __ldg(reinterpret_cast<const int4*>(adj_row) + (base >> 2));
        int rr[EPT] = {r4.x, r4.y, r4.z, r4.w};
#pragma unroll
        for (int k = 0; k < EPT; k++) {
            int r = rr[k];
            if ((__ldg(&g_flags[r >> 5]) >> (r & 31)) & 1u) {
                int idx = atomicAdd(&s_cnt, 1);
                if (idx < MAX_HITS) s_hits[idx] = make_int2(base + k, r);
            }
        }
    }
    __syncthreads();

    // ---- drain phase: all warps share the hit list; half-warp per hit ----
    int n = s_cnt < MAX_HITS ? s_cnt : MAX_HITS;
    int lane = tid & 31;
    int wid  = tid >> 5;                            // 0..7
    int half = lane >> 4;
    int l    = lane & 15;

    for (int h = wid * 2 + half; h < n; h += 16) {
        int2 hit = s_hits[h];                       // LDS, broadcast per half
        int   i  = hit.x;
        int   r  = hit.y;
        int   c  = __ldg(adj_col + i);              // broadcast (same addr per half)
        float v  = __ldg(adj_val + i);
        const float* src = (c < N_USER)
                               ? (user_emb + (size_t)c * D)
                               : (item_emb + (size_t)(c - N_USER) * D);
        float4 e = __ldg(reinterpret_cast<const float4*>(src) + l);
        float* dst = g_acc + (size_t)r * D + l * 4;
        asm volatile("red.global.add.v4.f32 [%0], {%1, %2, %3, %4};"
                     :: "l"(dst),
                        "f"(v * e.x), "f"(v * e.y), "f"(v * e.z), "f"(v * e.w)
                     : "memory");
    }
}

// ---------------------------------------------------------------------------
// K4: out[slot] = (e0[row] + 3*acc[row]) / 4. Two slots per warp (float4),
// and restore the flag bitset to all-zero for the next graph replay.
// ---------------------------------------------------------------------------
__global__ void k_gather_out(const int* __restrict__ users,
                             const int* __restrict__ pos,
                             const int* __restrict__ neg,
                             const float* __restrict__ user_emb,
                             const float* __restrict__ item_emb,
                             float* __restrict__ out) {
    int gtid = blockIdx.x * blockDim.x + threadIdx.x;
    int warp = gtid >> 5;
    int lane = gtid & 31;
    int half = lane >> 4;
    int l    = lane & 15;
    int s = warp * 2 + half;
    if (s >= NSLOTS) return;
    int r = slot_row(s, users, pos, neg);

    if (l == 0) g_flags[r >> 5] = 0u;               // racing zeros — benign

    const float* e0 = (r < N_USER) ? (user_emb + (size_t)r * D)
                                   : (item_emb + (size_t)(r - N_USER) * D);
    float4 e = __ldg(reinterpret_cast<const float4*>(e0) + l);
    float4 a = *(reinterpret_cast<const float4*>(g_acc + (size_t)r * D) + l);
    float4 o;
    o.x = (e.x + 3.0f * a.x) * 0.25f;
    o.y = (e.y + 3.0f * a.y) * 0.25f;
    o.z = (e.z + 3.0f * a.z) * 0.25f;
    o.w = (e.w + 3.0f * a.w) * 0.25f;
    reinterpret_cast<float4*>(out)[(size_t)s * (D / 4) + l] = o;
}

// ---------------------------------------------------------------------------
// launch
// ---------------------------------------------------------------------------
extern "C" void kernel_launch(void* const* d_in, const int* in_sizes, int n_in,
                              void* d_out, int out_size) {
    const int*   users    = (const int*)d_in[0];
    const int*   pos      = (const int*)d_in[1];
    const int*   neg      = (const int*)d_in[2];
    // d_in[3] mask, d_in[4] norm_adj: unused placeholders
    const float* user_emb = (const float*)d_in[5];
    const float* item_emb = (const float*)d_in[6];
    const int*   adj_row  = (const int*)d_in[7];
    const int*   adj_col  = (const int*)d_in[8];
    const float* adj_val  = (const float*)d_in[9];
    float* out = (float*)d_out;

    (void)in_sizes; (void)n_in; (void)out_size;

    {   // K2: mark + zero (2 slots per warp)
        int warps = (NSLOTS + 1) / 2;
        int threads = 256;
        int blocks = (warps * 32 + threads - 1) / threads;
        k_mark_and_zero<<<blocks, threads>>>(users, pos, neg);
    }
    {   // K3: staged filtered SpMM
        int blocks = (NNZ + EDGES_PER_BLOCK - 1) / EDGES_PER_BLOCK;
        k_spmm_filtered<<<blocks, SCAN_THREADS>>>(adj_row, adj_col, adj_val,
                                                  user_emb, item_emb);
    }
    {   // K4: gather outputs + reset flags (2 slots per warp)
        int warps = (NSLOTS + 1) / 2;
        int threads = 256;
        int blocks = (warps * 32 + threads - 1) / threads;
        k_gather_out<<<blocks, threads>>>(users, pos, neg, user_emb, item_emb, out);
    }
}